// round 1
// baseline (speedup 1.0000x reference)
#include <cuda_runtime.h>
#include <cuda_bf16.h>
#include <math.h>

// ---------------------------------------------------------------------------
// Problem: bs=16, c_in=c_out=512, w_dim=512, L=2048, k=3, UP=DOWN=2, 17-tap LPF
// Inputs (metadata order):
//  0: x        (16,512,2048) f32
//  1: w        (16,512)      f32
//  2: affine_w (512,512)     f32
//  3: affine_b (512,)        f32
//  4: conv_w   (512,512,3)   f32
//  5: conv_b   (512,)        f32
//  6: norm_ema ()            f32
// Output: (16,512,2048) f32
// ---------------------------------------------------------------------------

#define BS   16
#define CIN  512
#define COUT 512
#define LEN  2048
#define WDIM 512

// ---------------- device scratch (static: no allocation at launch time) ----
__device__ float g_cond[BS * CIN];        // cond[b,c]
__device__ float g_w2[COUT * CIN];        // sum_k conv_w[o,i,k]^2
__device__ float g_invw[COUT];            // rsqrt(mean_{i,k} conv_w^2)
__device__ float g_scale[BS * COUT];      // d[b,o] * invw[o]
__device__ float g_inv_s;                 // rsqrt(mean cond^2)
__device__ float g_y[BS * COUT * LEN];    // conv output, 64 MB

struct Filt { float up[17]; float dn[17]; };

// ---------------- K1: cond[b,c] = w[b,:] . affine_w[c,:] + affine_b[c] -----
__global__ void cond_kernel(const float* __restrict__ w,
                            const float* __restrict__ aw,
                            const float* __restrict__ ab) {
    int warp = (blockIdx.x * blockDim.x + threadIdx.x) >> 5;  // = c
    int lane = threadIdx.x & 31;
    if (warp >= CIN) return;
    int c = warp;
    float a[16];
#pragma unroll
    for (int t = 0; t < 16; t++) a[t] = aw[c * WDIM + lane + 32 * t];
    float bias = ab[c];
    for (int b = 0; b < BS; b++) {
        float acc = 0.f;
#pragma unroll
        for (int t = 0; t < 16; t++)
            acc = fmaf(a[t], w[b * WDIM + lane + 32 * t], acc);
#pragma unroll
        for (int s = 16; s; s >>= 1) acc += __shfl_xor_sync(0xffffffffu, acc, s);
        if (lane == 0) g_cond[b * CIN + c] = acc + bias;
    }
}

// ---------------- K2: g_inv_s = rsqrt(mean(cond^2)) ------------------------
__global__ void reduce_cond_kernel() {
    __shared__ float sm[256];
    float s = 0.f;
    for (int i = threadIdx.x; i < BS * CIN; i += 256) {
        float v = g_cond[i];
        s = fmaf(v, v, s);
    }
    sm[threadIdx.x] = s;
    __syncthreads();
    for (int off = 128; off; off >>= 1) {
        if (threadIdx.x < off) sm[threadIdx.x] += sm[threadIdx.x + off];
        __syncthreads();
    }
    if (threadIdx.x == 0) g_inv_s = rsqrtf(sm[0] / (float)(BS * CIN));
}

// ---------------- K3: per-o weight stats -----------------------------------
__global__ void wstats_kernel(const float* __restrict__ cw) {
    int o = blockIdx.x;
    __shared__ float sm[128];
    float tot = 0.f;
    for (int i = threadIdx.x; i < CIN; i += 128) {
        const float* p = cw + (size_t)o * (CIN * 3) + i * 3;
        float s3 = p[0] * p[0] + p[1] * p[1] + p[2] * p[2];
        g_w2[o * CIN + i] = s3;
        tot += s3;
    }
    sm[threadIdx.x] = tot;
    __syncthreads();
    for (int off = 64; off; off >>= 1) {
        if (threadIdx.x < off) sm[threadIdx.x] += sm[threadIdx.x + off];
        __syncthreads();
    }
    if (threadIdx.x == 0) g_invw[o] = rsqrtf(sm[0] / (float)(CIN * 3));
}

// ---------------- K4: g_scale[b,o] = rsqrt(invw^2 inv_s^2 * dot + 1e-8)*invw
__global__ void demod_kernel() {
    int warp = (blockIdx.x * blockDim.x + threadIdx.x) >> 5;  // = o
    int lane = threadIdx.x & 31;
    if (warp >= COUT) return;
    int o = warp;
    float a[16];
#pragma unroll
    for (int t = 0; t < 16; t++) a[t] = g_w2[o * CIN + lane + 32 * t];
    float invw = g_invw[o];
    float inv_s = g_inv_s;
    float f = invw * invw * inv_s * inv_s;
    for (int b = 0; b < BS; b++) {
        float acc = 0.f;
#pragma unroll
        for (int t = 0; t < 16; t++) {
            float cv = g_cond[b * CIN + lane + 32 * t];
            acc = fmaf(a[t], cv * cv, acc);
        }
#pragma unroll
        for (int s = 16; s; s >>= 1) acc += __shfl_xor_sync(0xffffffffu, acc, s);
        if (lane == 0) g_scale[b * COUT + o] = rsqrtf(f * acc + 1e-8f) * invw;
    }
}

// ---------------- K5: modulated conv (implicit GEMM, register tiled) -------
// Block: 64 out-ch x 128 L ; 256 threads (16 tx x 16 ty); 4 o x 8 l / thread.
#define BO 64
#define BL 128
#define CI 16

__global__ void __launch_bounds__(256)
conv_kernel(const float* __restrict__ x,
            const float* __restrict__ conv_w,
            const float* __restrict__ conv_b,
            const float* __restrict__ norm_ema) {
    __shared__ float xs[CI][BL + 2];
    __shared__ float ws[BO * CI * 3];

    int tx = threadIdx.x & 15;
    int ty = threadIdx.x >> 4;
    int l0 = blockIdx.x * BL;
    int o0 = blockIdx.y * BO;
    int b  = blockIdx.z;

    float rsn   = rsqrtf(norm_ema[0]);
    float inv_s = g_inv_s;
    float xscale_base = inv_s * rsn;

    float acc[4][8];
#pragma unroll
    for (int r = 0; r < 4; r++)
#pragma unroll
        for (int j = 0; j < 8; j++) acc[r][j] = 0.f;

    const float* xb = x + (size_t)b * CIN * LEN;

    for (int i0 = 0; i0 < CIN; i0 += CI) {
        // load x tile (scaled by per-channel style)
        for (int idx = threadIdx.x; idx < CI * (BL + 2); idx += 256) {
            int ci = idx / (BL + 2);
            int p  = idx - ci * (BL + 2);
            int gl = l0 - 1 + p;
            int i  = i0 + ci;
            float v = 0.f;
            if (gl >= 0 && gl < LEN) v = xb[i * LEN + gl];
            xs[ci][p] = v * (g_cond[b * CIN + i] * xscale_base);
        }
        // load weight tile (raw conv_w; o-scales applied in epilogue)
        for (int idx = threadIdx.x; idx < BO * CI * 3; idx += 256) {
            int oo = idx / (CI * 3);
            int r  = idx - oo * (CI * 3);
            ws[idx] = conv_w[(size_t)(o0 + oo) * (CIN * 3) + i0 * 3 + r];
        }
        __syncthreads();

#pragma unroll 2
        for (int ci = 0; ci < CI; ci++) {
#pragma unroll
            for (int kk = 0; kk < 3; kk++) {
                float xv[8];
#pragma unroll
                for (int j = 0; j < 8; j++) xv[j] = xs[ci][tx + 16 * j + kk];
#pragma unroll
                for (int r = 0; r < 4; r++) {
                    float wv = ws[(ty * 4 + r) * (CI * 3) + ci * 3 + kk];
#pragma unroll
                    for (int j = 0; j < 8; j++)
                        acc[r][j] = fmaf(wv, xv[j], acc[r][j]);
                }
            }
        }
        __syncthreads();
    }

#pragma unroll
    for (int r = 0; r < 4; r++) {
        int o = o0 + ty * 4 + r;
        float sc = g_scale[b * COUT + o];
        float bb = conv_b[o];
#pragma unroll
        for (int j = 0; j < 8; j++) {
            int l = l0 + tx + 16 * j;
            g_y[((size_t)(b * COUT + o)) * LEN + l] = fmaf(acc[r][j], sc, bb);
        }
    }
}

// ---------------- K6: fused up-LPF -> lrelu*sqrt2 -> down-LPF -> ::2 -------
// One block per (b,c) row.
__global__ void __launch_bounds__(256)
resample_kernel(float* __restrict__ out, Filt F) {
    __shared__ float ysm[LEN + 16];      // y[-8 .. 2055]
    __shared__ float usm[2 * LEN + 16];  // ylr[-8 .. 4103]
    int bc = blockIdx.x;
    const float* yrow = g_y + (size_t)bc * LEN;
    int t = threadIdx.x;

    if (t < 8) {
        ysm[t] = 0.f; ysm[LEN + 8 + t] = 0.f;
        usm[t] = 0.f; usm[2 * LEN + 8 + t] = 0.f;
    }
    for (int i = t; i < LEN; i += 256) ysm[8 + i] = yrow[i];
    __syncthreads();

    const float s2 = 1.41421356237f;
    for (int q = t; q < LEN; q += 256) {
        // even upsample index m = 2q : taps Uf[0,2,...,16] on y[q-4 .. q+4]
        float ue = 0.f;
#pragma unroll
        for (int p = 0; p < 9; p++) ue = fmaf(F.up[2 * p], ysm[q + 4 + p], ue);
        // odd m = 2q+1 : taps Uf[1,3,...,15] on y[q-3 .. q+4]
        float uo = 0.f;
#pragma unroll
        for (int p = 0; p < 8; p++) uo = fmaf(F.up[2 * p + 1], ysm[q + 5 + p], uo);
        usm[8 + 2 * q]     = (ue > 0.f ? ue : 0.1f * ue) * s2;
        usm[8 + 2 * q + 1] = (uo > 0.f ? uo : 0.1f * uo) * s2;
    }
    __syncthreads();

    float* orow = out + (size_t)bc * LEN;
    for (int tt = t; tt < LEN; tt += 256) {
        float z = 0.f;
#pragma unroll
        for (int k = 0; k < 17; k++) z = fmaf(F.dn[k], usm[2 * tt + k], z);
        orow[tt] = z;
    }
}

// ---------------- host: Kaiser-sinc filter (matches np.kaiser + ref) -------
static double bessel_i0(double x) {
    double s = 1.0, term = 1.0;
    for (int k = 1; k < 64; k++) {
        double h = x / (2.0 * k);
        term *= h * h;
        s += term;
        if (term < 1e-18 * s) break;
    }
    return s;
}

static void make_filter(float* f) {
    const double PI = 3.14159265358979323846;
    double i0b = bessel_i0(2.5);
    for (int i = 0; i < 17; i++) {
        int n = i - 8;
        float fv;
        if (n == 0) fv = 0.5f;
        else fv = (float)sin(0.5 * PI * (double)n) / ((float)(PI * (double)n) + 1e-8f);
        double r = (double)n / 8.0;
        double win = bessel_i0(2.5 * sqrt(1.0 - r * r)) / i0b;
        f[i] = (float)win * fv;
    }
}

// ---------------- launcher -------------------------------------------------
extern "C" void kernel_launch(void* const* d_in, const int* in_sizes, int n_in,
                              void* d_out, int out_size) {
    const float* x        = (const float*)d_in[0];
    const float* w        = (const float*)d_in[1];
    const float* affine_w = (const float*)d_in[2];
    const float* affine_b = (const float*)d_in[3];
    const float* conv_w   = (const float*)d_in[4];
    const float* conv_b   = (const float*)d_in[5];
    const float* norm_ema = (const float*)d_in[6];
    float* out = (float*)d_out;

    Filt F;
    make_filter(F.up);
    make_filter(F.dn);  // UP==DOWN==2 -> identical filters, kept separate

    cond_kernel<<<64, 256>>>(w, affine_w, affine_b);
    reduce_cond_kernel<<<1, 256>>>();
    wstats_kernel<<<COUT, 128>>>(conv_w);
    demod_kernel<<<64, 256>>>();

    dim3 cgrid(LEN / BL, COUT / BO, BS);
    conv_kernel<<<cgrid, 256>>>(x, conv_w, conv_b, norm_ema);

    resample_kernel<<<BS * COUT, 256>>>(out, F);
}

// round 2
// speedup vs baseline: 1.9361x; 1.9361x over previous
#include <cuda_runtime.h>
#include <cuda_bf16.h>
#include <math.h>
#include <stdint.h>

// ---------------------------------------------------------------------------
// bs=16, c_in=c_out=512, w_dim=512, L=2048, k=3, UP=DOWN=2, 17-tap Kaiser LPF
// Strategy: 3xBF16 split-precision implicit GEMM on HMMA (mma.sync m16n8k16)
// ---------------------------------------------------------------------------

#define BS   16
#define CIN  512
#define COUT 512
#define LEN  2048
#define WDIM 512

// ---------------- device scratch -------------------------------------------
__device__ float    g_cond[BS * CIN];
__device__ float    g_w2[COUT * CIN];
__device__ float    g_invw[COUT];
__device__ float    g_scale[BS * COUT];      // d[b,o] * invw[o]
__device__ float    g_inv_s;
__device__ float    g_y[BS * COUT * LEN];    // conv output (64 MB)
__device__ uint32_t g_xs[BS * CIN * LEN];    // packed (hi,lo) bf16 of scaled x (64 MB)
__device__ uint32_t g_wsp[3 * COUT * CIN];   // packed (hi,lo) bf16 of conv_w, [kk][o][i] (3 MB)

struct Filt { float up[17]; float dn[17]; };

// ---------------- helpers --------------------------------------------------
__device__ __forceinline__ uint32_t split2(float v) {
    __nv_bfloat16 h = __float2bfloat16(v);
    float r = v - __bfloat162float(h);
    __nv_bfloat16 l = __float2bfloat16(r);
    return (uint32_t)__bfloat16_as_ushort(h) | ((uint32_t)__bfloat16_as_ushort(l) << 16);
}

// ---------------- K1: cond[b,c] --------------------------------------------
__global__ void cond_kernel(const float* __restrict__ w,
                            const float* __restrict__ aw,
                            const float* __restrict__ ab) {
    int warp = (blockIdx.x * blockDim.x + threadIdx.x) >> 5;
    int lane = threadIdx.x & 31;
    if (warp >= CIN) return;
    int c = warp;
    float a[16];
#pragma unroll
    for (int t = 0; t < 16; t++) a[t] = aw[c * WDIM + lane + 32 * t];
    float bias = ab[c];
    for (int b = 0; b < BS; b++) {
        float acc = 0.f;
#pragma unroll
        for (int t = 0; t < 16; t++)
            acc = fmaf(a[t], w[b * WDIM + lane + 32 * t], acc);
#pragma unroll
        for (int s = 16; s; s >>= 1) acc += __shfl_xor_sync(0xffffffffu, acc, s);
        if (lane == 0) g_cond[b * CIN + c] = acc + bias;
    }
}

// ---------------- K2: inv_s ------------------------------------------------
__global__ void reduce_cond_kernel() {
    __shared__ float sm[256];
    float s = 0.f;
    for (int i = threadIdx.x; i < BS * CIN; i += 256) {
        float v = g_cond[i];
        s = fmaf(v, v, s);
    }
    sm[threadIdx.x] = s;
    __syncthreads();
    for (int off = 128; off; off >>= 1) {
        if (threadIdx.x < off) sm[threadIdx.x] += sm[threadIdx.x + off];
        __syncthreads();
    }
    if (threadIdx.x == 0) g_inv_s = rsqrtf(sm[0] / (float)(BS * CIN));
}

// ---------------- K3: weight stats -----------------------------------------
__global__ void wstats_kernel(const float* __restrict__ cw) {
    int o = blockIdx.x;
    __shared__ float sm[128];
    float tot = 0.f;
    for (int i = threadIdx.x; i < CIN; i += 128) {
        const float* p = cw + (size_t)o * (CIN * 3) + i * 3;
        float s3 = p[0] * p[0] + p[1] * p[1] + p[2] * p[2];
        g_w2[o * CIN + i] = s3;
        tot += s3;
    }
    sm[threadIdx.x] = tot;
    __syncthreads();
    for (int off = 64; off; off >>= 1) {
        if (threadIdx.x < off) sm[threadIdx.x] += sm[threadIdx.x + off];
        __syncthreads();
    }
    if (threadIdx.x == 0) g_invw[o] = rsqrtf(sm[0] / (float)(CIN * 3));
}

// ---------------- K4: demod scale ------------------------------------------
__global__ void demod_kernel() {
    int warp = (blockIdx.x * blockDim.x + threadIdx.x) >> 5;
    int lane = threadIdx.x & 31;
    if (warp >= COUT) return;
    int o = warp;
    float a[16];
#pragma unroll
    for (int t = 0; t < 16; t++) a[t] = g_w2[o * CIN + lane + 32 * t];
    float invw = g_invw[o];
    float inv_s = g_inv_s;
    float f = invw * invw * inv_s * inv_s;
    for (int b = 0; b < BS; b++) {
        float acc = 0.f;
#pragma unroll
        for (int t = 0; t < 16; t++) {
            float cv = g_cond[b * CIN + lane + 32 * t];
            acc = fmaf(a[t], cv * cv, acc);
        }
#pragma unroll
        for (int s = 16; s; s >>= 1) acc += __shfl_xor_sync(0xffffffffu, acc, s);
        if (lane == 0) g_scale[b * COUT + o] = rsqrtf(f * acc + 1e-8f) * invw;
    }
}

// ---------------- K5a: split weights to (hi,lo) bf16, [kk][o][i] -----------
__global__ void split_w_kernel(const float* __restrict__ cw) {
    int idx = blockIdx.x * blockDim.x + threadIdx.x;
    if (idx >= 3 * COUT * CIN) return;
    int i  = idx & (CIN - 1);
    int o  = (idx >> 9) & (COUT - 1);
    int kk = idx >> 18;
    float v = cw[(size_t)(o * CIN + i) * 3 + kk];
    g_wsp[idx] = split2(v);
}

// ---------------- K5b: split x (scaled) to (hi,lo) bf16 --------------------
__global__ void split_x_kernel(const float* __restrict__ x,
                               const float* __restrict__ norm_ema) {
    float base = rsqrtf(norm_ema[0]) * g_inv_s;
    int idx4 = blockIdx.x * blockDim.x + threadIdx.x;   // quad index
    if (idx4 >= (BS * CIN * LEN) / 4) return;
    int row = idx4 >> 9;                                 // (b*512+i), 512 quads per row
    float sc = base * g_cond[row];
    float4 v = ((const float4*)x)[idx4];
    uint4 r;
    r.x = split2(v.x * sc);
    r.y = split2(v.y * sc);
    r.z = split2(v.z * sc);
    r.w = split2(v.w * sc);
    ((uint4*)g_xs)[idx4] = r;
}

// ---------------- K6: modulated conv via mma.sync (3xBF16) -----------------
// Block tile: 128 o x 128 l, per batch. 8 warps: (wm 0..3) x (wn 0..1),
// warp tile 32 o x 64 l = 2 m16 x 8 n8 fragments.
// K layout per 16-channel chunk: 48 slots: slot 3j+{0,1,2} =
//   A: {w_hi, w_hi, w_lo}[j]   B: {x_hi, x_lo, x_hi}[j]
#define BO   128
#define BLT  128
#define CI   16
#define XPAD 56          // bf16 units per smem row (28 words: conflict-free frags)
#define XROWS (BLT + 2)
#define WROWS (3 * BO)
#define CONV_SMEM ((XROWS + WROWS) * XPAD * 2)

__device__ __forceinline__ void mma16816(float* c, const uint32_t a[4],
                                         uint32_t b0, uint32_t b1) {
    asm volatile(
        "mma.sync.aligned.m16n8k16.row.col.f32.bf16.bf16.f32 "
        "{%0,%1,%2,%3}, {%4,%5,%6,%7}, {%8,%9}, {%0,%1,%2,%3};"
        : "+f"(c[0]), "+f"(c[1]), "+f"(c[2]), "+f"(c[3])
        : "r"(a[0]), "r"(a[1]), "r"(a[2]), "r"(a[3]), "r"(b0), "r"(b1));
}

__global__ void __launch_bounds__(256)
conv_mma_kernel(const float* __restrict__ conv_b) {
    extern __shared__ unsigned short smem[];
    unsigned short* xsm = smem;                  // [XROWS][XPAD]
    unsigned short* wsm = smem + XROWS * XPAD;   // [3*BO][XPAD]

    int tid  = threadIdx.x;
    int warp = tid >> 5;
    int lane = tid & 31;
    int grp  = lane >> 2;
    int tig  = lane & 3;
    int wm   = warp >> 1;   // 0..3
    int wn   = warp & 1;    // 0..1

    int l0 = blockIdx.x * BLT;
    int o0 = blockIdx.y * BO;
    int b  = blockIdx.z;

    float acc[2][8][4];
#pragma unroll
    for (int mt = 0; mt < 2; mt++)
#pragma unroll
        for (int nt = 0; nt < 8; nt++)
#pragma unroll
            for (int r = 0; r < 4; r++) acc[mt][nt][r] = 0.f;

    const uint32_t* xrow = g_xs + ((size_t)b * CIN) * LEN;

    for (int ic = 0; ic < CIN / CI; ic++) {
        // ---- stage x: xsm[n][3j+{0,1,2}] = {hi, lo, hi} of xs[ic*16+j][l0-1+n]
        for (int idx = tid; idx < XROWS * CI; idx += 256) {
            int j = idx / XROWS;
            int n = idx - j * XROWS;
            int gl = l0 - 1 + n;
            uint32_t v = 0;
            if (gl >= 0 && gl < LEN) v = xrow[(ic * CI + j) * LEN + gl];
            unsigned short hi = (unsigned short)(v & 0xffffu);
            unsigned short lo = (unsigned short)(v >> 16);
            unsigned short* p = xsm + n * XPAD + 3 * j;
            p[0] = hi; p[1] = lo; p[2] = hi;
        }
        // ---- stage w: wsm[kk*BO+o][3j+{0,1,2}] = {hi, hi, lo}
        for (int idx = tid; idx < 3 * BO * CI; idx += 256) {
            int j  = idx & (CI - 1);
            int rest = idx >> 4;
            int o  = rest & (BO - 1);
            int kk = rest >> 7;
            uint32_t v = g_wsp[((kk * COUT) + o0 + o) * CIN + ic * CI + j];
            unsigned short hi = (unsigned short)(v & 0xffffu);
            unsigned short lo = (unsigned short)(v >> 16);
            unsigned short* p = wsm + (kk * BO + o) * XPAD + 3 * j;
            p[0] = hi; p[1] = hi; p[2] = lo;
        }
        __syncthreads();

        // ---- compute: 3 shifts x 3 k16-tiles
#pragma unroll
        for (int kk = 0; kk < 3; kk++) {
#pragma unroll
            for (int k16 = 0; k16 < 3; k16++) {
                int col = k16 * 16 + 2 * tig;
                uint32_t a[2][4];
#pragma unroll
                for (int mt = 0; mt < 2; mt++) {
                    const unsigned short* wp =
                        wsm + (kk * BO + wm * 32 + mt * 16 + grp) * XPAD + col;
                    a[mt][0] = *(const uint32_t*)(wp);
                    a[mt][1] = *(const uint32_t*)(wp + 8 * XPAD);
                    a[mt][2] = *(const uint32_t*)(wp + 8);
                    a[mt][3] = *(const uint32_t*)(wp + 8 * XPAD + 8);
                }
#pragma unroll
                for (int nt = 0; nt < 8; nt++) {
                    const unsigned short* xp =
                        xsm + (wn * 64 + nt * 8 + grp + kk) * XPAD + col;
                    uint32_t b0 = *(const uint32_t*)(xp);
                    uint32_t b1 = *(const uint32_t*)(xp + 8);
                    mma16816(acc[0][nt], a[0], b0, b1);
                    mma16816(acc[1][nt], a[1], b0, b1);
                }
            }
        }
        __syncthreads();
    }

    // ---- epilogue: per-o scale + bias, write y
#pragma unroll
    for (int mt = 0; mt < 2; mt++) {
        int oA = o0 + wm * 32 + mt * 16 + grp;
        int oB = oA + 8;
        float scA = g_scale[b * COUT + oA], bbA = conv_b[oA];
        float scB = g_scale[b * COUT + oB], bbB = conv_b[oB];
#pragma unroll
        for (int nt = 0; nt < 8; nt++) {
            int l = l0 + wn * 64 + nt * 8 + 2 * tig;
            float2 vA = make_float2(fmaf(acc[mt][nt][0], scA, bbA),
                                    fmaf(acc[mt][nt][1], scA, bbA));
            float2 vB = make_float2(fmaf(acc[mt][nt][2], scB, bbB),
                                    fmaf(acc[mt][nt][3], scB, bbB));
            *(float2*)&g_y[((size_t)(b * COUT + oA)) * LEN + l] = vA;
            *(float2*)&g_y[((size_t)(b * COUT + oB)) * LEN + l] = vB;
        }
    }
}

// ---------------- K7: fused up-LPF -> lrelu*sqrt2 -> down-LPF -> ::2 -------
__global__ void __launch_bounds__(256)
resample_kernel(float* __restrict__ out, Filt F) {
    __shared__ float ysm[LEN + 16];
    __shared__ float usm[2 * LEN + 16];
    int bc = blockIdx.x;
    const float* yrow = g_y + (size_t)bc * LEN;
    int t = threadIdx.x;

    if (t < 8) {
        ysm[t] = 0.f; ysm[LEN + 8 + t] = 0.f;
        usm[t] = 0.f; usm[2 * LEN + 8 + t] = 0.f;
    }
    for (int i = t; i < LEN; i += 256) ysm[8 + i] = yrow[i];
    __syncthreads();

    const float s2 = 1.41421356237f;
    for (int q = t; q < LEN; q += 256) {
        float ue = 0.f;
#pragma unroll
        for (int p = 0; p < 9; p++) ue = fmaf(F.up[2 * p], ysm[q + 4 + p], ue);
        float uo = 0.f;
#pragma unroll
        for (int p = 0; p < 8; p++) uo = fmaf(F.up[2 * p + 1], ysm[q + 5 + p], uo);
        usm[8 + 2 * q]     = (ue > 0.f ? ue : 0.1f * ue) * s2;
        usm[8 + 2 * q + 1] = (uo > 0.f ? uo : 0.1f * uo) * s2;
    }
    __syncthreads();

    float* orow = out + (size_t)bc * LEN;
    for (int tt = t; tt < LEN; tt += 256) {
        float z = 0.f;
#pragma unroll
        for (int k = 0; k < 17; k++) z = fmaf(F.dn[k], usm[2 * tt + k], z);
        orow[tt] = z;
    }
}

// ---------------- host: Kaiser-sinc filter ---------------------------------
static double bessel_i0(double x) {
    double s = 1.0, term = 1.0;
    for (int k = 1; k < 64; k++) {
        double h = x / (2.0 * k);
        term *= h * h;
        s += term;
        if (term < 1e-18 * s) break;
    }
    return s;
}

static void make_filter(float* f) {
    const double PI = 3.14159265358979323846;
    double i0b = bessel_i0(2.5);
    for (int i = 0; i < 17; i++) {
        int n = i - 8;
        float fv;
        if (n == 0) fv = 0.5f;
        else fv = (float)sin(0.5 * PI * (double)n) / ((float)(PI * (double)n) + 1e-8f);
        double r = (double)n / 8.0;
        double win = bessel_i0(2.5 * sqrt(1.0 - r * r)) / i0b;
        f[i] = (float)win * fv;
    }
}

// ---------------- launcher -------------------------------------------------
extern "C" void kernel_launch(void* const* d_in, const int* in_sizes, int n_in,
                              void* d_out, int out_size) {
    const float* x        = (const float*)d_in[0];
    const float* w        = (const float*)d_in[1];
    const float* affine_w = (const float*)d_in[2];
    const float* affine_b = (const float*)d_in[3];
    const float* conv_w   = (const float*)d_in[4];
    const float* conv_b   = (const float*)d_in[5];
    const float* norm_ema = (const float*)d_in[6];
    float* out = (float*)d_out;

    Filt F;
    make_filter(F.up);
    make_filter(F.dn);

    cudaFuncSetAttribute(conv_mma_kernel,
                         cudaFuncAttributeMaxDynamicSharedMemorySize, CONV_SMEM);

    cond_kernel<<<64, 256>>>(w, affine_w, affine_b);
    reduce_cond_kernel<<<1, 256>>>();
    wstats_kernel<<<COUT, 128>>>(conv_w);
    demod_kernel<<<64, 256>>>();
    split_w_kernel<<<(3 * COUT * CIN + 255) / 256, 256>>>(conv_w);
    split_x_kernel<<<(BS * CIN * LEN / 4 + 255) / 256, 256>>>(x, norm_ema);

    dim3 cgrid(LEN / BLT, COUT / BO, BS);
    conv_mma_kernel<<<cgrid, 256, CONV_SMEM>>>(conv_b);

    resample_kernel<<<BS * COUT, 256>>>(out, F);
}